// round 4
// baseline (speedup 1.0000x reference)
#include <cuda_runtime.h>
#include <math.h>

// ---------------- scratch (no allocation allowed; __device__ globals) --------
#define MAX_N 100000
__device__ float g_proj[MAX_N * 32];   // [n][0:16]=z@W1a, [n][16:32]=z@W1b  (12.8 MB)

// packed f32x2 FMA (Blackwell FFMA2 — PTX-only, ptxas never auto-fuses)
#define FMA_F32X2(acc, a, b) \
    asm("fma.rn.f32x2 %0, %1, %2, %0;" : "+l"(acc) : "l"(a), "l"(b))

// ---------------- kernel 1: per-node projection  proj = z @ W1c --------------
// block = 256 threads = 8 warps; warp computes 8 nodes x 32 cols (lane = col).
// W1 transposed in-block into sW[s][lane] float4 layout (conflict-free LDS.128).
// Inner product uses packed f32x2 FMA: 2 k-values per instruction.
#define PROJ_BLOCK 256
#define NODES_PER_WARP 8
#define NODES_PER_BLOCK 64   // 8 warps * 8 nodes

__global__ __launch_bounds__(PROJ_BLOCK, 2) void proj_kernel(
    const float* __restrict__ z, const float* __restrict__ W1, int N)
{
    __shared__ float4 sZ[NODES_PER_BLOCK * 32];   // 64 nodes x 128 f32 = 32 KB
    __shared__ float4 sW[32 * 32];                // 16 KB, [s*32 + lane] = k-quad
    const int tid = threadIdx.x;
    const int node0 = blockIdx.x * NODES_PER_BLOCK;

    // in-block W1 transpose: flat float idx -> (s,lane,j), k = 4s+j
    #pragma unroll
    for (int i = 0; i < (32 * 128) / PROJ_BLOCK; i++) {
        int idx = tid + i * PROJ_BLOCK;
        int j = idx & 3;
        int l = (idx >> 2) & 31;
        int s = idx >> 7;
        int k = 4 * s + j;
        float v = (l < 16) ? __ldg(W1 + k * 16 + l)
                           : __ldg(W1 + (128 + k) * 16 + (l - 16));
        ((float*)sW)[idx] = v;
    }

    const float4* z4 = (const float4*)z;
    #pragma unroll
    for (int i = 0; i < (NODES_PER_BLOCK * 32) / PROJ_BLOCK; i++) {
        int idx = tid + i * PROJ_BLOCK;
        int n = node0 + (idx >> 5);
        sZ[idx] = (n < N) ? z4[(size_t)n * 32 + (idx & 31)]
                          : make_float4(0.f, 0.f, 0.f, 0.f);
    }
    __syncthreads();

    const int warp = tid >> 5;
    const int lane = tid & 31;                       // = output column c
    const ulonglong2* zbase = (const ulonglong2*)(sZ + (warp * NODES_PER_WARP) * 32);
    const ulonglong2* sW2   = (const ulonglong2*)sW;

    unsigned long long acc[NODES_PER_WARP];          // each = packed {sum_even, sum_odd}
    #pragma unroll
    for (int n = 0; n < NODES_PER_WARP; n++) acc[n] = 0ull;

    #pragma unroll 8
    for (int s = 0; s < 32; s++) {
        ulonglong2 wv = sW2[s * 32 + lane];          // conflict-free LDS.128
        #pragma unroll
        for (int n = 0; n < NODES_PER_WARP; n++) {
            ulonglong2 zv = zbase[n * 32 + s];       // LDS.128 broadcast
            FMA_F32X2(acc[n], zv.x, wv.x);
            FMA_F32X2(acc[n], zv.y, wv.y);
        }
    }

    #pragma unroll
    for (int n = 0; n < NODES_PER_WARP; n++) {
        int node = node0 + warp * NODES_PER_WARP + n;
        if (node < N) {
            float2 p = *(float2*)&acc[n];
            g_proj[(size_t)node * 32 + lane] = p.x + p.y;   // coalesced 128B
        }
    }
}

// ---------------- kernel 2: per-edge dual head (2 edges / warp) --------------
// 16 lanes per edge. Each lane loads 2 float4 of z_row/z_col (512B per row,
// coalesced), 4-butterfly dot reduce. The 16 lanes directly own the 16 hidden
// units of the MLP head (proj gather: 64B per side), 4-butterfly reduce.
__global__ __launch_bounds__(256) void edge_kernel(
    const float* __restrict__ z,
    const int* __restrict__ ei,            // int32 (jax x64 disabled)
    const float* __restrict__ b1,
    const float* __restrict__ W2,
    const float* __restrict__ b2,
    float* __restrict__ out,
    int E)
{
    const int group = (int)((blockIdx.x * blockDim.x + threadIdx.x) >> 4);  // edge id
    const int l = threadIdx.x & 15;
    const bool valid = (group < E);
    const int e = valid ? group : (E - 1);           // clamp; keep warp converged

    const int row = __ldg(ei + e);
    const int col = __ldg(ei + (size_t)E + e);

    const float4* zr = (const float4*)z + (size_t)row * 32;
    const float4* zc = (const float4*)z + (size_t)col * 32;
    float4 a0 = __ldg(zr + l);
    float4 a1 = __ldg(zr + l + 16);
    float4 b0 = __ldg(zc + l);
    float4 b1v = __ldg(zc + l + 16);

    float dot = a0.x * b0.x + a0.y * b0.y + a0.z * b0.z + a0.w * b0.w
              + a1.x * b1v.x + a1.y * b1v.y + a1.z * b1v.z + a1.w * b1v.w;

    // MLP head: h_l = projA[row][l] + projB[col][l] + b1[l]
    float pa = g_proj[row * 32 + l];
    float pb = g_proj[col * 32 + 16 + l];
    float h  = fmaxf(pa + pb + __ldg(b1 + l), 0.f);
    float t  = h * __ldg(W2 + l);

    #pragma unroll
    for (int off = 8; off; off >>= 1) {
        dot += __shfl_xor_sync(0xFFFFFFFFu, dot, off);
        t   += __shfl_xor_sync(0xFFFFFFFFu, t, off);
    }

    if (l == 0 && valid) {
        out[e] = dot;
        float x = t + __ldg(b2);
        // softplus = max(x,0) + log1p(exp(-|x|))
        out[(size_t)E + e] = fmaxf(x, 0.f) + log1pf(__expf(-fabsf(x)));
    }
}

// ---------------- launch ----------------------------------------------------
extern "C" void kernel_launch(void* const* d_in, const int* in_sizes, int n_in,
                              void* d_out, int out_size) {
    const float* z  = (const float*)d_in[0];      // [N,128] f32
    const int*   ei = (const int*)d_in[1];        // [2,E] int32
    const float* W1 = (const float*)d_in[2];      // [256,16]
    const float* b1 = (const float*)d_in[3];      // [16]
    const float* W2 = (const float*)d_in[4];      // [16,1]
    const float* b2 = (const float*)d_in[5];      // [1]
    float* out = (float*)d_out;                   // [2E]: adj_logits | weights

    const int N = in_sizes[0] / 128;
    const int E = in_sizes[1] / 2;

    proj_kernel<<<(N + NODES_PER_BLOCK - 1) / NODES_PER_BLOCK, PROJ_BLOCK>>>(z, W1, N);
    edge_kernel<<<((size_t)E * 16 + 255) / 256, 256>>>(z, ei, b1, W2, b2, out, E);
}

// round 5
// speedup vs baseline: 1.0235x; 1.0235x over previous
#include <cuda_runtime.h>
#include <math.h>

// ---------------- scratch (no allocation allowed; __device__ globals) --------
#define MAX_N 100000
__device__ float  g_proj[MAX_N * 32];  // [n][0:16]=z@W1a, [n][16:32]=z@W1b+b1  (12.8 MB)
__device__ float4 g_Wfmt[32 * 32];     // [s][l] = {W1c[4s+j][l], j=0..3}  (16 KB)

// packed f32x2 FMA (Blackwell FFMA2 — PTX-only, ptxas never auto-fuses)
#define FMA_F32X2(acc, a, b) \
    asm("fma.rn.f32x2 %0, %1, %2, %0;" : "+l"(acc) : "l"(a), "l"(b))

// ---------------- kernel 0: one-time W1 reformat into [s][l][4] --------------
__global__ void prep_W_kernel(const float* __restrict__ W1) {
    int idx = blockIdx.x * blockDim.x + threadIdx.x;   // flat float index 0..4095
    if (idx >= 32 * 128) return;
    int j = idx & 3;
    int l = (idx >> 2) & 31;
    int s = idx >> 7;
    int k = 4 * s + j;
    float v = (l < 16) ? W1[k * 16 + l] : W1[(128 + k) * 16 + (l - 16)];
    ((float*)g_Wfmt)[idx] = v;
}

// ---------------- kernel 1: per-node projection  proj = z @ W1c --------------
// block = 256 threads = 8 warps; warp computes 8 nodes x 32 cols (lane = col).
// Weights staged via coalesced 16KB copy into sW[s][lane] (conflict-free LDS.128).
// Inner product uses packed f32x2 FMA: 2 k-values per instruction.
#define PROJ_BLOCK 256
#define NODES_PER_WARP 8
#define NODES_PER_BLOCK 64   // 8 warps * 8 nodes

__global__ __launch_bounds__(PROJ_BLOCK, 2) void proj_kernel(
    const float* __restrict__ z, const float* __restrict__ b1, int N)
{
    __shared__ float4 sZ[NODES_PER_BLOCK * 32];   // 64 nodes x 128 f32 = 32 KB
    __shared__ float4 sW[32 * 32];                // 16 KB, [s*32 + lane] = k-quad
    const int tid = threadIdx.x;
    const int node0 = blockIdx.x * NODES_PER_BLOCK;

    // coalesced 16KB weight copy (L2-hot after first wave)
    #pragma unroll
    for (int i = 0; i < 1024 / PROJ_BLOCK; i++)
        sW[tid + i * PROJ_BLOCK] = g_Wfmt[tid + i * PROJ_BLOCK];

    const float4* z4 = (const float4*)z;
    #pragma unroll
    for (int i = 0; i < (NODES_PER_BLOCK * 32) / PROJ_BLOCK; i++) {
        int idx = tid + i * PROJ_BLOCK;
        int n = node0 + (idx >> 5);
        sZ[idx] = (n < N) ? z4[(size_t)n * 32 + (idx & 31)]
                          : make_float4(0.f, 0.f, 0.f, 0.f);
    }
    __syncthreads();

    const int warp = tid >> 5;
    const int lane = tid & 31;                       // = output column c
    const ulonglong2* zbase = (const ulonglong2*)(sZ + (warp * NODES_PER_WARP) * 32);
    const ulonglong2* sW2   = (const ulonglong2*)sW;

    unsigned long long acc[NODES_PER_WARP];          // packed {sum_even, sum_odd}
    #pragma unroll
    for (int n = 0; n < NODES_PER_WARP; n++) acc[n] = 0ull;

    #pragma unroll 8
    for (int s = 0; s < 32; s++) {
        ulonglong2 wv = sW2[s * 32 + lane];          // conflict-free LDS.128
        #pragma unroll
        for (int n = 0; n < NODES_PER_WARP; n++) {
            ulonglong2 zv = zbase[n * 32 + s];       // LDS.128 broadcast
            FMA_F32X2(acc[n], zv.x, wv.x);
            FMA_F32X2(acc[n], zv.y, wv.y);
        }
    }

    // fold b1 into the col-side (cols 16..31) so edge kernel skips it
    const float bias = (lane >= 16) ? __ldg(b1 + lane - 16) : 0.f;

    #pragma unroll
    for (int n = 0; n < NODES_PER_WARP; n++) {
        int node = node0 + warp * NODES_PER_WARP + n;
        if (node < N) {
            float2 p = *(float2*)&acc[n];
            g_proj[(size_t)node * 32 + lane] = p.x + p.y + bias;  // coalesced 128B
        }
    }
}

// ---------------- kernel 2: per-edge dual head (2 edges / warp) --------------
// 16 lanes per edge. Each lane loads 2 float4 of z_row/z_col (512B per row,
// coalesced at the 128B-line floor), 4-butterfly dot reduce. The 16 lanes own
// the 16 hidden units of the MLP head (proj gather: 64B per side).
__global__ __launch_bounds__(256) void edge_kernel(
    const float* __restrict__ z,
    const int* __restrict__ ei,            // int32 (jax x64 disabled)
    const float* __restrict__ W2,
    const float* __restrict__ b2,
    float* __restrict__ out,
    int E)
{
    const int group = (int)((blockIdx.x * blockDim.x + threadIdx.x) >> 4);  // edge id
    const int l = threadIdx.x & 15;
    const bool valid = (group < E);
    const int e = valid ? group : (E - 1);           // clamp; keep warp converged

    const int row = __ldg(ei + e);
    const int col = __ldg(ei + (size_t)E + e);

    const float4* zr = (const float4*)z + (size_t)row * 32;
    const float4* zc = (const float4*)z + (size_t)col * 32;
    float4 a0 = __ldg(zr + l);
    float4 a1 = __ldg(zr + l + 16);
    float4 b0 = __ldg(zc + l);
    float4 b1v = __ldg(zc + l + 16);

    float dot = a0.x * b0.x + a0.y * b0.y + a0.z * b0.z + a0.w * b0.w
              + a1.x * b1v.x + a1.y * b1v.y + a1.z * b1v.z + a1.w * b1v.w;

    // MLP head: h_l = projA[row][l] + (projB[col][l] + b1[l])   (b1 pre-folded)
    float pa = g_proj[row * 32 + l];
    float pb = g_proj[col * 32 + 16 + l];
    float h  = fmaxf(pa + pb, 0.f);
    float t  = h * __ldg(W2 + l);

    #pragma unroll
    for (int off = 8; off; off >>= 1) {
        dot += __shfl_xor_sync(0xFFFFFFFFu, dot, off);
        t   += __shfl_xor_sync(0xFFFFFFFFu, t, off);
    }

    if (l == 0 && valid) {
        out[e] = dot;
        float x = t + __ldg(b2);
        // softplus = max(x,0) + log1p(exp(-|x|))
        out[(size_t)E + e] = fmaxf(x, 0.f) + log1pf(__expf(-fabsf(x)));
    }
}

// ---------------- launch ----------------------------------------------------
extern "C" void kernel_launch(void* const* d_in, const int* in_sizes, int n_in,
                              void* d_out, int out_size) {
    const float* z  = (const float*)d_in[0];      // [N,128] f32
    const int*   ei = (const int*)d_in[1];        // [2,E] int32
    const float* W1 = (const float*)d_in[2];      // [256,16]
    const float* b1 = (const float*)d_in[3];      // [16]
    const float* W2 = (const float*)d_in[4];      // [16,1]
    const float* b2 = (const float*)d_in[5];      // [1]
    float* out = (float*)d_out;                   // [2E]: adj_logits | weights

    const int N = in_sizes[0] / 128;
    const int E = in_sizes[1] / 2;

    prep_W_kernel<<<(32 * 128 + 255) / 256, 256>>>(W1);
    proj_kernel<<<(N + NODES_PER_BLOCK - 1) / NODES_PER_BLOCK, PROJ_BLOCK>>>(z, b1, N);
    edge_kernel<<<((size_t)E * 16 + 255) / 256, 256>>>(z, ei, W2, b2, out, E);
}